// round 10
// baseline (speedup 1.0000x reference)
#include <cuda_runtime.h>
#include <math.h>

// Hawkes univariate NLL — ONE block, 1024 threads, BOTH rows in one pass.
// Sorted x =>  S[j] = exp(-w x_j) * P[j] - dup(j),
//              P[j] = exclusive prefix of exp(w x_i).
// The two independent row-scans share the same shuffle/barrier skeleton
// (2 FADDs per scan step, pure ILP). No inter-block handshake, no fences,
// no atomics: thread 0 writes the scalar directly.

#define HK_N       8192
#define HK_THREADS 1024
#define HK_VPT     8
#define HK_T       1.0f
#define HK_REG     0.01f

__device__ __forceinline__ float fast_rcp(float a) {
    float r;
    asm("rcp.approx.f32 %0, %1;" : "=f"(r) : "f"(a));
    return r;
}

// exp(d) for small d in [0, ~0.03]: cubic Horner, rel err < 1e-8.
__device__ __forceinline__ float exp_small(float d) {
    return fmaf(d, fmaf(d, fmaf(d, 0.16666667f, 0.5f), 1.0f), 1.0f);
}

__global__ __launch_bounds__(HK_THREADS)
void hawkes_kernel(const float* __restrict__ x,
                   const float* __restrict__ mu_p,
                   const float* __restrict__ alpha_p,
                   const float* __restrict__ w_p,
                   float* __restrict__ out) {
    __shared__ float warp_scan0[32], warp_scan1[32];
    __shared__ float warp_last0[32], warp_last1[32];
    __shared__ float red[32];

    const int tid = threadIdx.x;
    const unsigned lane = tid & 31u;
    const unsigned wid  = tid >> 5;

    const float mu    = *mu_p;
    const float alpha = *alpha_p;
    const float w     = *w_p;
    const float aw    = alpha * w;
    const float emwT  = __expf(-w * HK_T);

    // Epilogue constant — params only; overlaps with the row work.
    float base_const = 0.0f;
    if (tid == 0)
        base_const = mu * HK_T
                   + HK_REG * (-__logf(mu) - __logf(alpha) - __logf(w));

    const int base = tid * HK_VPT;
    const float* __restrict__ x0 = x;
    const float* __restrict__ x1 = x + HK_N;

    // ---- load 8 contiguous values per row (4x float4, front-batched) ----
    float a[HK_VPT], bv[HK_VPT];
    {
        const float4 a0 = *reinterpret_cast<const float4*>(x0 + base);
        const float4 a1 = *reinterpret_cast<const float4*>(x0 + base + 4);
        const float4 b0 = *reinterpret_cast<const float4*>(x1 + base);
        const float4 b1 = *reinterpret_cast<const float4*>(x1 + base + 4);
        a[0]=a0.x; a[1]=a0.y; a[2]=a0.z; a[3]=a0.w;
        a[4]=a1.x; a[5]=a1.y; a[6]=a1.z; a[7]=a1.w;
        bv[0]=b0.x; bv[1]=b0.y; bv[2]=b0.z; bv[3]=b0.w;
        bv[4]=b1.x; bv[5]=b1.y; bv[6]=b1.z; bv[7]=b1.w;
    }

    // ---- e = exp(w*x): 1 MUFU exp + 7 incremental cubics, per row ----
    float ea[HK_VPT], eb[HK_VPT];
    ea[0] = __expf(w * a[0]);
    eb[0] = __expf(w * bv[0]);
    #pragma unroll
    for (int k = 1; k < HK_VPT; k++) {
        ea[k] = ea[k - 1] * exp_small(w * (a[k]  - a[k - 1]));
        eb[k] = eb[k - 1] * exp_small(w * (bv[k] - bv[k - 1]));
    }

    // depth-3 trees for thread totals + exclusive prefixes (both rows)
    const float a01 = ea[0]+ea[1], a23 = ea[2]+ea[3];
    const float a45 = ea[4]+ea[5], a67 = ea[6]+ea[7];
    const float a03 = a01+a23,     a47 = a45+a67;
    const float runA = a03 + a47;
    const float b01 = eb[0]+eb[1], b23 = eb[2]+eb[3];
    const float b45 = eb[4]+eb[5], b67 = eb[6]+eb[7];
    const float b03 = b01+b23,     b47 = b45+b67;
    const float runB = b03 + b47;

    float pa[HK_VPT], pb[HK_VPT];
    pa[0]=0.0f;      pa[1]=ea[0];      pa[2]=a01;      pa[3]=a01+ea[2];
    pa[4]=a03;       pa[5]=a03+ea[4];  pa[6]=a03+a45;  pa[7]=a03+a45+ea[6];
    pb[0]=0.0f;      pb[1]=eb[0];      pb[2]=b01;      pb[3]=b01+eb[2];
    pb[4]=b03;       pb[5]=b03+eb[4];  pb[6]=b03+b45;  pb[7]=b03+b45+eb[6];

    // ---- warp inclusive scans of thread totals (2 independent chains) ----
    float vA = runA, vB = runB;
    #pragma unroll
    for (int off = 1; off < 32; off <<= 1) {
        float nA = __shfl_up_sync(0xffffffffu, vA, off);
        float nB = __shfl_up_sync(0xffffffffu, vB, off);
        if (lane >= (unsigned)off) { vA += nA; vB += nB; }
    }
    const float prevA_in = __shfl_up_sync(0xffffffffu, a[HK_VPT-1], 1);
    const float prevB_in = __shfl_up_sync(0xffffffffu, bv[HK_VPT-1], 1);
    if (lane == 31u) {
        warp_scan0[wid] = vA;  warp_scan1[wid] = vB;
        warp_last0[wid] = a[HK_VPT-1];  warp_last1[wid] = bv[HK_VPT-1];
    }
    __syncthreads();

    // ---- every warp redundantly scans the 32 warp totals (both rows) ----
    float wtA = warp_scan0[lane], wtB = warp_scan1[lane];
    #pragma unroll
    for (int off = 1; off < 32; off <<= 1) {
        float nA = __shfl_up_sync(0xffffffffu, wtA, off);
        float nB = __shfl_up_sync(0xffffffffu, wtB, off);
        if (lane >= (unsigned)off) { wtA += nA; wtB += nB; }
    }
    const float warp_exclA = (wid > 0) ? __shfl_sync(0xffffffffu, wtA, wid-1) : 0.0f;
    const float warp_exclB = (wid > 0) ? __shfl_sync(0xffffffffu, wtB, wid-1) : 0.0f;
    const float rowTotA = __shfl_sync(0xffffffffu, wtA, 31);
    const float rowTotB = __shfl_sync(0xffffffffu, wtB, 31);

    const float exclA = (vA - runA) + warp_exclA;
    const float exclB = (vB - runB) + warp_exclB;

    float prevA = -1.0f, prevB = -1.0f;          // x >= 0: never equal
    if (tid > 0) {
        prevA = (lane == 0u) ? warp_last0[wid-1] : prevA_in;
        prevB = (lane == 0u) ? warp_last1[wid-1] : prevB_in;
    }

    // ---- duplicate-run counts per row (register chains; global walk only
    //      if a run crosses a thread boundary — astronomically rare) ----
    float ca[HK_VPT], cb[HK_VPT];
    {
        float c0 = 0.0f;
        if (a[0] == prevA) {
            int pq = base - 1;
            while (pq >= 0 && x0[pq] == a[0]) { c0 += 1.0f; --pq; }
        }
        ca[0] = c0;
        float c1 = 0.0f;
        if (bv[0] == prevB) {
            int pq = base - 1;
            while (pq >= 0 && x1[pq] == bv[0]) { c1 += 1.0f; --pq; }
        }
        cb[0] = c1;
        #pragma unroll
        for (int k = 1; k < HK_VPT; k++) {
            ca[k] = (a[k]  == a[k-1])  ? ca[k-1] + 1.0f : 0.0f;
            cb[k] = (bv[k] == bv[k-1]) ? cb[k-1] + 1.0f : 0.0f;
        }
    }

    // ---- elementwise with fused logs, both rows:
    //      A_k = mu*e_k + aw*P_k;  log(mu + aw*P/e) = log(A) - w*x ----
    float acc = 0.0f, sumx = 0.0f;
    float A0[HK_VPT], A1[HK_VPT];
    #pragma unroll
    for (int k = 0; k < HK_VPT; k++) {
        const float PA = exclA + pa[k];
        const float PB = exclB + pb[k];
        if (ca[k] == 0.0f) {
            A0[k] = fmaf(mu, ea[k], aw * PA);
            sumx += a[k];
        } else {
            A0[k] = 1.0f;
            float S = PA * fast_rcp(ea[k]) - ca[k];
            if (S < 0.0f) S = 0.0f;
            acc -= __logf(fmaf(aw, S, mu));
        }
        if (cb[k] == 0.0f) {
            A1[k] = fmaf(mu, eb[k], aw * PB);
            sumx += bv[k];
        } else {
            A1[k] = 1.0f;
            float S = PB * fast_rcp(eb[k]) - cb[k];
            if (S < 0.0f) S = 0.0f;
            acc -= __logf(fmaf(aw, S, mu));
        }
    }
    const float prod0 = (A0[0]*A0[1]) * (A0[2]*A0[3]);
    const float prod1 = (A0[4]*A0[5]) * (A0[6]*A0[7]);
    const float prod2 = (A1[0]*A1[1]) * (A1[2]*A1[3]);
    const float prod3 = (A1[4]*A1[5]) * (A1[6]*A1[7]);
    acc -= (__logf(prod0) + __logf(prod1)) + (__logf(prod2) + __logf(prod3));
    acc = fmaf(w, sumx, acc);

    // closed-form neg for BOTH rows, added once
    if (tid == 0)
        acc += alpha * (2.0f * (float)HK_N - emwT * (rowTotA + rowTotB));

    // ---- block reduction ----
    #pragma unroll
    for (int off = 16; off > 0; off >>= 1)
        acc += __shfl_down_sync(0xffffffffu, acc, off);
    if (lane == 0u) red[wid] = acc;
    __syncthreads();
    if (wid == 0) {
        float r = red[lane];
        #pragma unroll
        for (int off = 16; off > 0; off >>= 1)
            r += __shfl_down_sync(0xffffffffu, r, off);
        if (lane == 0u)
            out[0] = base_const + r;     // single writer, no handshake
    }
}

extern "C" void kernel_launch(void* const* d_in, const int* in_sizes, int n_in,
                              void* d_out, int out_size) {
    const float* x     = (const float*)d_in[0];
    const float* mu    = (const float*)d_in[1];
    const float* alpha = (const float*)d_in[2];
    const float* w     = (const float*)d_in[3];
    float* out = (float*)d_out;

    hawkes_kernel<<<1, HK_THREADS>>>(x, mu, alpha, w, out);
}

// round 11
// speedup vs baseline: 1.2353x; 1.2353x over previous
#include <cuda_runtime.h>
#include <math.h>

// Hawkes univariate NLL — single launch, 4 blocks (2 rows x 2 halves).
// Sorted x =>  S[j] = exp(-w x_j) * P[j] - dup(j),
//              P[j] = exclusive prefix of exp(w x_i).
// Lesson from R3/R10: inter-block flag handoffs between symmetric blocks are
// ~free (overlapped), serial per-SM work is what costs. So: halve per-block
// work (VPT=4) and pay one overlapped mid-row total handoff per row.
//  * h=0 publishes its half-total right after its scan (early);
//    h=1 consumes it right after its own scan (same time) -> spin ~ 0.
//  * 1 MUFU exp + 3 incremental cubics; ONE fused logf per thread.
//  * neg term closed form per half (exactly additive across halves).
//  * tail: 3 publishers -> block 0 sums in fixed order (deterministic).

#define HK_N       8192
#define HK_HALF    4096
#define HK_THREADS 1024
#define HK_VPT     4
#define HK_T       1.0f
#define HK_REG     0.01f

__device__ volatile float g_half[2];    // per-row first-half totals
__device__ volatile int   g_hflag[2];   // zero-init; reset by block 0
__device__ volatile float g_part[4];    // per-block partials
__device__ volatile int   g_pflag[4];   // zero-init; reset by block 0

__device__ __forceinline__ float fast_rcp(float a) {
    float r;
    asm("rcp.approx.f32 %0, %1;" : "=f"(r) : "f"(a));
    return r;
}

// exp(d) for small d in [0, ~0.03]: cubic Horner, rel err < 1e-8.
__device__ __forceinline__ float exp_small(float d) {
    return fmaf(d, fmaf(d, fmaf(d, 0.16666667f, 0.5f), 1.0f), 1.0f);
}

__global__ __launch_bounds__(HK_THREADS)
void hawkes_kernel(const float* __restrict__ x,
                   const float* __restrict__ mu_p,
                   const float* __restrict__ alpha_p,
                   const float* __restrict__ w_p,
                   float* __restrict__ out) {
    __shared__ float warp_scan[32];
    __shared__ float warp_last[32];
    __shared__ float red[32];

    const int blk = blockIdx.x;          // 0:(r0,h0) 1:(r0,h1) 2:(r1,h0) 3:(r1,h1)
    const int row = blk >> 1;
    const int h   = blk & 1;
    const int tid = threadIdx.x;
    const unsigned lane = tid & 31u;
    const unsigned wid  = tid >> 5;

    const float mu    = *mu_p;
    const float alpha = *alpha_p;
    const float w     = *w_p;
    const float aw    = alpha * w;
    const float emwT  = __expf(-w * HK_T);

    float base_const = 0.0f;
    if (blk == 0 && tid == 0)
        base_const = mu * HK_T
                   + HK_REG * (-__logf(mu) - __logf(alpha) - __logf(w));

    const float* __restrict__ xr = x + (size_t)row * HK_N;
    const int base = h * HK_HALF + tid * HK_VPT;

    // mid-boundary prev value for h=1/tid=0 (prefetch early, overlaps)
    float prev_boundary = -1.0f;                 // x >= 0: never equal
    if (h == 1 && tid == 0) prev_boundary = xr[HK_HALF - 1];

    // ---- load 4 contiguous values (one float4, coalesced) ----
    float xv[HK_VPT];
    {
        const float4 a0 = *reinterpret_cast<const float4*>(xr + base);
        xv[0]=a0.x; xv[1]=a0.y; xv[2]=a0.z; xv[3]=a0.w;
    }

    // ---- e = exp(w*x): 1 MUFU exp + 3 incremental cubics ----
    float e[HK_VPT];
    e[0] = __expf(w * xv[0]);
    #pragma unroll
    for (int k = 1; k < HK_VPT; k++)
        e[k] = e[k - 1] * exp_small(w * (xv[k] - xv[k - 1]));

    const float t01 = e[0] + e[1], t23 = e[2] + e[3];
    const float run = t01 + t23;

    float p[HK_VPT];
    p[0] = 0.0f;  p[1] = e[0];  p[2] = t01;  p[3] = t01 + e[2];

    // ---- warp inclusive scan of thread totals ----
    float v = run;
    #pragma unroll
    for (int off = 1; off < 32; off <<= 1) {
        float n = __shfl_up_sync(0xffffffffu, v, off);
        if (lane >= (unsigned)off) v += n;
    }
    const float prev_in_warp = __shfl_up_sync(0xffffffffu, xv[HK_VPT - 1], 1);
    if (lane == 31u) {
        warp_scan[wid] = v;
        warp_last[wid] = xv[HK_VPT - 1];
    }
    __syncthreads();

    // ---- every warp redundantly scans the 32 warp totals ----
    float wt = warp_scan[lane];
    #pragma unroll
    for (int off = 1; off < 32; off <<= 1) {
        float n = __shfl_up_sync(0xffffffffu, wt, off);
        if (lane >= (unsigned)off) wt += n;
    }
    const float warp_excl = (wid > 0)
        ? __shfl_sync(0xffffffffu, wt, wid - 1) : 0.0f;
    const float half_total = __shfl_sync(0xffffffffu, wt, 31);

    float thread_excl = (v - run) + warp_excl;

    // ---- mid-row handoff (overlapped: both sides arrive here together) ----
    if (h == 0) {
        if (tid == 0) {
            g_half[row] = half_total;
            __threadfence();
            g_hflag[row] = 1;
        }
    } else {
        while (g_hflag[row] == 0) { }            // spin ~0 (symmetric blocks)
        thread_excl += g_half[row];              // volatile read after flag
    }

    float prev_last = prev_boundary;
    if (tid > 0)
        prev_last = (lane == 0u) ? warp_last[wid - 1] : prev_in_warp;

    // ---- duplicate-run counts (register chain; global walk only if a run
    //      crosses a thread boundary — astronomically rare) ----
    float c[HK_VPT];
    {
        float c0 = 0.0f;
        if (xv[0] == prev_last) {
            int pq = base - 1;
            while (pq >= 0 && xr[pq] == xv[0]) { c0 += 1.0f; --pq; }
        }
        c[0] = c0;
        #pragma unroll
        for (int k = 1; k < HK_VPT; k++)
            c[k] = (xv[k] == xv[k - 1]) ? c[k - 1] + 1.0f : 0.0f;
    }

    // ---- elementwise with fused logs:
    //      A_k = mu*e_k + aw*P_k;  log(mu + aw*P/e) = log(A) - w*x ----
    float acc = 0.0f, sumx = 0.0f;
    float A[HK_VPT];
    #pragma unroll
    for (int k = 0; k < HK_VPT; k++) {
        const float P = thread_excl + p[k];
        if (c[k] == 0.0f) {
            A[k] = fmaf(mu, e[k], aw * P);
            sumx += xv[k];
        } else {
            A[k] = 1.0f;
            float S = P * fast_rcp(e[k]) - c[k];
            if (S < 0.0f) S = 0.0f;
            acc -= __logf(fmaf(aw, S, mu));
        }
    }
    acc -= __logf((A[0] * A[1]) * (A[2] * A[3]));   // ONE logf per thread
    acc = fmaf(w, sumx, acc);

    // closed-form neg for this half, added once
    if (tid == 0)
        acc += alpha * ((float)HK_HALF - emwT * half_total);

    // ---- block reduction ----
    #pragma unroll
    for (int off = 16; off > 0; off >>= 1)
        acc += __shfl_down_sync(0xffffffffu, acc, off);
    if (lane == 0u) red[wid] = acc;
    __syncthreads();
    if (wid == 0) {
        float r = red[lane];
        #pragma unroll
        for (int off = 16; off > 0; off >>= 1)
            r += __shfl_down_sync(0xffffffffu, r, off);
        if (lane == 0u) {
            if (blk != 0) {
                g_part[blk] = r;
                __threadfence();
                g_pflag[blk] = 1;
            } else {
                while (g_pflag[1] == 0) { }
                while (g_pflag[2] == 0) { }
                while (g_pflag[3] == 0) { }
                __threadfence();
                const float sum = ((r + g_part[1]) + g_part[2]) + g_part[3];
                out[0] = base_const + sum;           // fixed order
                // reset all flags for the next graph replay
                g_pflag[1] = 0; g_pflag[2] = 0; g_pflag[3] = 0;
                g_hflag[0] = 0; g_hflag[1] = 0;
            }
        }
    }
}

extern "C" void kernel_launch(void* const* d_in, const int* in_sizes, int n_in,
                              void* d_out, int out_size) {
    const float* x     = (const float*)d_in[0];
    const float* mu    = (const float*)d_in[1];
    const float* alpha = (const float*)d_in[2];
    const float* w     = (const float*)d_in[3];
    float* out = (float*)d_out;

    hawkes_kernel<<<4, HK_THREADS>>>(x, mu, alpha, w, out);
}

// round 12
// speedup vs baseline: 1.5484x; 1.2535x over previous
#include <cuda_runtime.h>
#include <math.h>

// Hawkes univariate NLL — single launch, 2 blocks (one per batch row).
// Sorted x =>  S[j] = exp(-w x_j) * P[j] - dup(j),
//              P[j] = exclusive prefix of exp(w x_i).
// Best-known structure (R7/R8) + tail micro-opt:
//  * single-atom 64-bit publish {tag|bits}: no threadfence, one L2 trip.
//  * base_const (3 logf) computed on block 1 (publisher) and folded into
//    the published value — off block 0's spin+write critical tail.
//  * log fusion: 2 logf/thread; plain parallel __expf (no serial chain).
//  * neg term closed form from the scan row total.

#define HK_N       8192
#define HK_THREADS 1024
#define HK_VPT     8
#define HK_T       1.0f
#define HK_REG     0.01f

__device__ volatile unsigned long long g_word;   // 0 = empty; {1<<32 | bits}

__device__ __forceinline__ float fast_rcp(float a) {
    float r;
    asm("rcp.approx.f32 %0, %1;" : "=f"(r) : "f"(a));
    return r;
}

__global__ __launch_bounds__(HK_THREADS)
void hawkes_kernel(const float* __restrict__ x,
                   const float* __restrict__ mu_p,
                   const float* __restrict__ alpha_p,
                   const float* __restrict__ w_p,
                   float* __restrict__ out) {
    __shared__ float warp_scan[32];
    __shared__ float warp_last[32];
    __shared__ float red[32];

    const int b   = blockIdx.x;
    const int tid = threadIdx.x;
    const unsigned lane = tid & 31u;
    const unsigned wid  = tid >> 5;

    const float mu    = *mu_p;
    const float alpha = *alpha_p;
    const float w     = *w_p;
    const float aw    = alpha * w;
    const float emwT  = __expf(-w * HK_T);

    // Epilogue constant on the PUBLISHER block (slack path), folded into
    // its published partial. Block 0's tail stays MUFU-free.
    float base_const = 0.0f;
    if (b == 1 && tid == 0)
        base_const = mu * HK_T
                   + HK_REG * (-__logf(mu) - __logf(alpha) - __logf(w));

    const float* __restrict__ xr = x + (size_t)b * HK_N;
    const int base = tid * HK_VPT;

    // ---- load 8 contiguous values (2x float4, coalesced) ----
    float xv[HK_VPT];
    {
        const float4 a0 = *reinterpret_cast<const float4*>(xr + base);
        const float4 a1 = *reinterpret_cast<const float4*>(xr + base + 4);
        xv[0]=a0.x; xv[1]=a0.y; xv[2]=a0.z; xv[3]=a0.w;
        xv[4]=a1.x; xv[5]=a1.y; xv[6]=a1.z; xv[7]=a1.w;
    }

    // ---- e = exp(w*x): 8 independent MUFU exps (parallel, no chain) ----
    float e[HK_VPT];
    #pragma unroll
    for (int k = 0; k < HK_VPT; k++) e[k] = __expf(w * xv[k]);

    // depth-3 tree for thread total + exclusive prefixes
    const float t01 = e[0] + e[1], t23 = e[2] + e[3];
    const float t45 = e[4] + e[5], t67 = e[6] + e[7];
    const float t03 = t01 + t23,   t47 = t45 + t67;
    const float run = t03 + t47;

    float p[HK_VPT];
    p[0] = 0.0f;        p[1] = e[0];
    p[2] = t01;         p[3] = t01 + e[2];
    p[4] = t03;         p[5] = t03 + e[4];
    p[6] = t03 + t45;   p[7] = t03 + t45 + e[6];

    // ---- warp inclusive scan of thread totals ----
    float v = run;
    #pragma unroll
    for (int off = 1; off < 32; off <<= 1) {
        float n = __shfl_up_sync(0xffffffffu, v, off);
        if (lane >= (unsigned)off) v += n;
    }
    const float prev_in_warp = __shfl_up_sync(0xffffffffu, xv[HK_VPT - 1], 1);
    if (lane == 31u) {
        warp_scan[wid] = v;
        warp_last[wid] = xv[HK_VPT - 1];
    }
    __syncthreads();

    // ---- every warp redundantly scans the 32 warp totals (one barrier) ----
    float wt = warp_scan[lane];
    #pragma unroll
    for (int off = 1; off < 32; off <<= 1) {
        float n = __shfl_up_sync(0xffffffffu, wt, off);
        if (lane >= (unsigned)off) wt += n;
    }
    const float warp_excl = (wid > 0)
        ? __shfl_sync(0xffffffffu, wt, wid - 1) : 0.0f;
    const float row_total = __shfl_sync(0xffffffffu, wt, 31);

    const float thread_excl = (v - run) + warp_excl;

    float prev_last = -1.0f;                     // x >= 0: never equal
    if (tid > 0)
        prev_last = (lane == 0u) ? warp_last[wid - 1] : prev_in_warp;

    // ---- duplicate-run counts (register chain; global walk only if a run
    //      crosses a thread boundary — astronomically rare) ----
    float c[HK_VPT];
    {
        float c0 = 0.0f;
        if (xv[0] == prev_last) {
            int pq = base - 1;
            while (pq >= 0 && xr[pq] == xv[0]) { c0 += 1.0f; --pq; }
        }
        c[0] = c0;
        #pragma unroll
        for (int k = 1; k < HK_VPT; k++)
            c[k] = (xv[k] == xv[k - 1]) ? c[k - 1] + 1.0f : 0.0f;
    }

    // ---- elementwise with fused logs:
    //      A_k = mu*e_k + aw*P_k;  log(mu + aw*P/e) = log(A) - w*x ----
    float acc = 0.0f, sumx = 0.0f;
    float A[HK_VPT];
    #pragma unroll
    for (int k = 0; k < HK_VPT; k++) {
        const float P = thread_excl + p[k];
        if (c[k] == 0.0f) {
            A[k] = fmaf(mu, e[k], aw * P);
            sumx += xv[k];
        } else {
            A[k] = 1.0f;
            float S = P * fast_rcp(e[k]) - c[k];
            if (S < 0.0f) S = 0.0f;
            acc -= __logf(fmaf(aw, S, mu));
        }
    }
    const float prod0 = (A[0] * A[1]) * (A[2] * A[3]);
    const float prod1 = (A[4] * A[5]) * (A[6] * A[7]);
    acc -= __logf(prod0) + __logf(prod1);
    acc = fmaf(w, sumx, acc);

    // closed-form neg for the whole row, added once
    if (tid == 0)
        acc += alpha * ((float)HK_N - emwT * row_total);

    // ---- block reduction ----
    #pragma unroll
    for (int off = 16; off > 0; off >>= 1)
        acc += __shfl_down_sync(0xffffffffu, acc, off);
    if (lane == 0u) red[wid] = acc;
    __syncthreads();
    if (wid == 0) {
        float r = red[lane];
        #pragma unroll
        for (int off = 16; off > 0; off >>= 1)
            r += __shfl_down_sync(0xffffffffu, r, off);
        if (lane == 0u) {
            if (b == 1) {
                // one 8-byte atom: {tag=1 | float bits}. No fence needed —
                // value and readiness travel together.
                const float payload = r + base_const;
                g_word = (1ULL << 32)
                       | (unsigned long long)__float_as_uint(payload);
            } else {
                unsigned long long m;
                do { m = g_word; } while ((m >> 32) == 0ULL);
                const float r1 = __uint_as_float((unsigned int)m);
                out[0] = r + r1;                 // fixed order: deterministic
                g_word = 0ULL;                   // reset for next replay
            }
        }
    }
}

extern "C" void kernel_launch(void* const* d_in, const int* in_sizes, int n_in,
                              void* d_out, int out_size) {
    const float* x     = (const float*)d_in[0];
    const float* mu    = (const float*)d_in[1];
    const float* alpha = (const float*)d_in[2];
    const float* w     = (const float*)d_in[3];
    float* out = (float*)d_out;

    const int total = in_sizes[0];
    const int B = total / HK_N;                 // B=2, N=8192 fixed
    hawkes_kernel<<<B, HK_THREADS>>>(x, mu, alpha, w, out);
}

// round 13
// speedup vs baseline: 1.6232x; 1.0483x over previous
#include <cuda_runtime.h>
#include <math.h>

// Hawkes univariate NLL — single launch, 2 blocks (one per batch row).
// Sorted x =>  S[j] = exp(-w x_j) * P[j] - dup(j),
//              P[j] = exclusive prefix of exp(w x_i).
// R12 skeleton (best known) + post-barrier chain shortening:
//  * A_k = (mu*e_k + aw*p_k) + aw*thread_excl : the first term (Abase) and
//    sumx are computed BEFORE the block-scan barrier; post-barrier work is
//    just 1 FMUL + 8 FADD + products + 2 logf.
//  * single-atom 64-bit publish {tag|bits}: no fence, one L2 trip.
//  * epilogue constant on the publisher block, folded into its payload.
//  * neg term closed form from the scan row total.

#define HK_N       8192
#define HK_THREADS 1024
#define HK_VPT     8
#define HK_T       1.0f
#define HK_REG     0.01f

__device__ volatile unsigned long long g_word;   // 0 = empty; {1<<32 | bits}

__device__ __forceinline__ float fast_rcp(float a) {
    float r;
    asm("rcp.approx.f32 %0, %1;" : "=f"(r) : "f"(a));
    return r;
}

__global__ __launch_bounds__(HK_THREADS)
void hawkes_kernel(const float* __restrict__ x,
                   const float* __restrict__ mu_p,
                   const float* __restrict__ alpha_p,
                   const float* __restrict__ w_p,
                   float* __restrict__ out) {
    __shared__ float warp_scan[32];
    __shared__ float warp_last[32];
    __shared__ float red[32];

    const int b   = blockIdx.x;
    const int tid = threadIdx.x;
    const unsigned lane = tid & 31u;
    const unsigned wid  = tid >> 5;

    const float mu    = *mu_p;
    const float alpha = *alpha_p;
    const float w     = *w_p;
    const float aw    = alpha * w;
    const float emwT  = __expf(-w * HK_T);

    // Epilogue constant on the PUBLISHER block (slack path).
    float base_const = 0.0f;
    if (b == 1 && tid == 0)
        base_const = mu * HK_T
                   + HK_REG * (-__logf(mu) - __logf(alpha) - __logf(w));

    const float* __restrict__ xr = x + (size_t)b * HK_N;
    const int base = tid * HK_VPT;

    // ---- load 8 contiguous values (2x float4, coalesced) ----
    float xv[HK_VPT];
    {
        const float4 a0 = *reinterpret_cast<const float4*>(xr + base);
        const float4 a1 = *reinterpret_cast<const float4*>(xr + base + 4);
        xv[0]=a0.x; xv[1]=a0.y; xv[2]=a0.z; xv[3]=a0.w;
        xv[4]=a1.x; xv[5]=a1.y; xv[6]=a1.z; xv[7]=a1.w;
    }

    // ---- e = exp(w*x): 8 independent MUFU exps ----
    float e[HK_VPT];
    #pragma unroll
    for (int k = 0; k < HK_VPT; k++) e[k] = __expf(w * xv[k]);

    // depth-3 tree for thread total + exclusive prefixes
    const float t01 = e[0] + e[1], t23 = e[2] + e[3];
    const float t45 = e[4] + e[5], t67 = e[6] + e[7];
    const float t03 = t01 + t23,   t47 = t45 + t67;
    const float run = t03 + t47;

    float p[HK_VPT];
    p[0] = 0.0f;        p[1] = e[0];
    p[2] = t01;         p[3] = t01 + e[2];
    p[4] = t03;         p[5] = t03 + e[4];
    p[6] = t03 + t45;   p[7] = t03 + t45 + e[6];

    // ---- PRE-BARRIER: Abase_k = mu*e_k + aw*p_k  and  sumx (tree) ----
    float Abase[HK_VPT];
    #pragma unroll
    for (int k = 0; k < HK_VPT; k++)
        Abase[k] = fmaf(mu, e[k], aw * p[k]);
    const float sx01 = xv[0]+xv[1], sx23 = xv[2]+xv[3];
    const float sx45 = xv[4]+xv[5], sx67 = xv[6]+xv[7];
    const float sumx_all = (sx01 + sx23) + (sx45 + sx67);

    // ---- warp inclusive scan of thread totals ----
    float v = run;
    #pragma unroll
    for (int off = 1; off < 32; off <<= 1) {
        float n = __shfl_up_sync(0xffffffffu, v, off);
        if (lane >= (unsigned)off) v += n;
    }
    const float prev_in_warp = __shfl_up_sync(0xffffffffu, xv[HK_VPT - 1], 1);
    if (lane == 31u) {
        warp_scan[wid] = v;
        warp_last[wid] = xv[HK_VPT - 1];
    }
    __syncthreads();

    // ---- every warp redundantly scans the 32 warp totals (one barrier) ----
    float wt = warp_scan[lane];
    #pragma unroll
    for (int off = 1; off < 32; off <<= 1) {
        float n = __shfl_up_sync(0xffffffffu, wt, off);
        if (lane >= (unsigned)off) wt += n;
    }
    const float warp_excl = (wid > 0)
        ? __shfl_sync(0xffffffffu, wt, wid - 1) : 0.0f;
    const float row_total = __shfl_sync(0xffffffffu, wt, 31);

    const float thread_excl = (v - run) + warp_excl;
    const float Q = aw * thread_excl;             // the only scan-dep factor

    float prev_last = -1.0f;                      // x >= 0: never equal
    if (tid > 0)
        prev_last = (lane == 0u) ? warp_last[wid - 1] : prev_in_warp;

    // ---- duplicate-run counts (register chain; global walk only if a run
    //      crosses a thread boundary — astronomically rare) ----
    float c[HK_VPT];
    {
        float c0 = 0.0f;
        if (xv[0] == prev_last) {
            int pq = base - 1;
            while (pq >= 0 && xr[pq] == xv[0]) { c0 += 1.0f; --pq; }
        }
        c[0] = c0;
        #pragma unroll
        for (int k = 1; k < HK_VPT; k++)
            c[k] = (xv[k] == xv[k - 1]) ? c[k - 1] + 1.0f : 0.0f;
    }

    // ---- POST-BARRIER: A_k = Abase_k + Q; fused logs ----
    float acc = 0.0f, sumx = sumx_all;
    float A[HK_VPT];
    #pragma unroll
    for (int k = 0; k < HK_VPT; k++) {
        if (c[k] == 0.0f) {
            A[k] = Abase[k] + Q;
        } else {
            A[k] = 1.0f;
            sumx -= xv[k];                        // remove from the -w*x fold
            const float P = thread_excl + p[k];
            float S = P * fast_rcp(e[k]) - c[k];
            if (S < 0.0f) S = 0.0f;
            acc -= __logf(fmaf(aw, S, mu));
        }
    }
    const float prod0 = (A[0] * A[1]) * (A[2] * A[3]);
    const float prod1 = (A[4] * A[5]) * (A[6] * A[7]);
    acc -= __logf(prod0) + __logf(prod1);
    acc = fmaf(w, sumx, acc);

    // closed-form neg for the whole row, added once
    if (tid == 0)
        acc += alpha * ((float)HK_N - emwT * row_total);

    // ---- block reduction ----
    #pragma unroll
    for (int off = 16; off > 0; off >>= 1)
        acc += __shfl_down_sync(0xffffffffu, acc, off);
    if (lane == 0u) red[wid] = acc;
    __syncthreads();
    if (wid == 0) {
        float r = red[lane];
        #pragma unroll
        for (int off = 16; off > 0; off >>= 1)
            r += __shfl_down_sync(0xffffffffu, r, off);
        if (lane == 0u) {
            if (b == 1) {
                // one 8-byte atom: value + readiness travel together.
                const float payload = r + base_const;
                g_word = (1ULL << 32)
                       | (unsigned long long)__float_as_uint(payload);
            } else {
                unsigned long long m;
                do { m = g_word; } while ((m >> 32) == 0ULL);
                const float r1 = __uint_as_float((unsigned int)m);
                out[0] = r + r1;                 // fixed order: deterministic
                g_word = 0ULL;                   // reset for next replay
            }
        }
    }
}

extern "C" void kernel_launch(void* const* d_in, const int* in_sizes, int n_in,
                              void* d_out, int out_size) {
    const float* x     = (const float*)d_in[0];
    const float* mu    = (const float*)d_in[1];
    const float* alpha = (const float*)d_in[2];
    const float* w     = (const float*)d_in[3];
    float* out = (float*)d_out;

    const int total = in_sizes[0];
    const int B = total / HK_N;                 // B=2, N=8192 fixed
    hawkes_kernel<<<B, HK_THREADS>>>(x, mu, alpha, w, out);
}